// round 9
// baseline (speedup 1.0000x reference)
#include <cuda_runtime.h>
#include <cstdint>

#define N_EDGES 250000
#define N_RBF   10
#define FEAT    144
#define P_TOTAL 4864
#define TILE_E  64
#define THREADS 512
#define NWARP   (THREADS / 32)          // 16
#define VSTRIDE 20                      // Rt w-row stride (16 used + 4 pad)
#define RSLICE  (16 * VSTRIDE)          // 320 floats per r-slice
#define RBUF    (N_RBF * RSLICE)        // 3200 floats per path slice/buffer
#define YS_STR  40                      // padded Ys per-edge stride
#define TMP_ESTR 88                     // tmp per-edge stride
#define TMP_WARP (4 * TMP_ESTR)         // 352 floats per warp
#define RADS_WARP 80                    // per-warp radial table
#define NPATH   19

// dynamic smem partition (floats)
#define OFF_RT   0
#define OFF_TMP  (OFF_RT + 3 * RBUF)                 // 9600
#define OFF_YS   (OFF_TMP + NWARP * TMP_WARP)        // 9600+5632=15232
#define OFF_RAD  (OFF_YS + TILE_E * YS_STR)          // 15232+2560=17792
#define SMEM_FLOATS (OFF_RAD + NWARP * RADS_WARP)    // 19072
#define SMEM_BYTES  (SMEM_FLOATS * 4)                // 76288

typedef unsigned long long u64;

__constant__ float cg_c[1225];
__device__ float R_pad[NPATH * RBUF];   // padded+transposed+norm-folded R

// ---- packed f32x2 helpers -------------------------------------------------
__device__ __forceinline__ u64 pack2(float lo, float hi) {
    u64 r; asm("mov.b64 %0, {%1,%2};" : "=l"(r) : "f"(lo), "f"(hi)); return r;
}
__device__ __forceinline__ void unpack2(u64 v, float& lo, float& hi) {
    asm("mov.b64 {%0,%1}, %2;" : "=f"(lo), "=f"(hi) : "l"(v));
}
__device__ __forceinline__ u64 ffma2(u64 a, u64 b, u64 c) {
    u64 d; asm("fma.rn.f32x2 %0, %1, %2, %3;" : "=l"(d) : "l"(a), "l"(b), "l"(c));
    return d;
}
__device__ __forceinline__ u64 fmul2(u64 a, u64 b) {
    u64 d; asm("mul.rn.f32x2 %0, %1, %2;" : "=l"(d) : "l"(a), "l"(b)); return d;
}
__device__ __forceinline__ u64 fadd2(u64 a, u64 b) {
    u64 d; asm("add.rn.f32x2 %0, %1, %2;" : "=l"(d) : "l"(a), "l"(b)); return d;
}

// ---------------------------------------------------------------------------
__global__ void prep_kernel(const float* __restrict__ R)
{
    const float norms[NPATH] = {
        1.0f, 0.57735026918962576f, 0.44721359549995794f,
        0.57735026918962576f, 1.0f, 0.57735026918962576f,
        0.44721359549995794f, 0.57735026918962576f,
        0.44721359549995794f, 0.37796447300922723f,
        0.44721359549995794f, 0.57735026918962576f,
        0.44721359549995794f, 0.37796447300922723f, 1.0f,
        0.57735026918962576f, 0.44721359549995794f,
        0.37796447300922723f, 0.33333333333333333f
    };
    int idx = blockIdx.x * blockDim.x + threadIdx.x;
    if (idx >= NPATH * RBUF) return;
    int p    = idx / RBUF,   rem  = idx - p * RBUF;
    int r    = rem / RSLICE; int rem2 = rem - r * RSLICE;
    int w    = rem2 / VSTRIDE, v = rem2 - w * VSTRIDE;
    float val = 0.f;
    if (v < 16)
        val = R[(size_t)r * P_TOTAL + p * 256 + w * 16 + v] * norms[p];
    R_pad[idx] = val;
}

// ---------------------------------------------------------------------------
template<int IO, int II, int LF, int CGOFF>
__device__ __forceinline__ void do_path(
    const u64 (&FAB)[9],
    const float* __restrict__ Ys_p,
    const float* __restrict__ Rt,
    float* __restrict__ tmp_w,
    const float* __restrict__ radS_w,
    int m, int eh, int lA, int lB, int leA,
    u64 (&acc)[4][5])
{
    constexpr int DOUT = 2 * IO + 1;
    constexpr int DI   = 2 * II + 1;
    constexpr int DF   = 2 * LF + 1;
    constexpr int FB0  = (II == 0) ? 0 : ((II == 1) ? 1 : 4);
    constexpr int YB   = (LF == 0) ? 0 : (LF == 1) ? 4 : (LF == 2) ? 12
                       : (LF == 3) ? 20 : 28;

    // ---- packed Ys ----
    u64 yAB[DF];
    {
        float ya[DF], yb[DF];
        const float* pa = Ys_p + lA * YS_STR + YB;
        const float* pb = Ys_p + lB * YS_STR + YB;
#pragma unroll
        for (int f4 = 0; f4 < DF / 4; f4++) {
            float4 qa = *(const float4*)(pa + 4 * f4);
            float4 qb = *(const float4*)(pb + 4 * f4);
            ya[4*f4+0]=qa.x; ya[4*f4+1]=qa.y; ya[4*f4+2]=qa.z; ya[4*f4+3]=qa.w;
            yb[4*f4+0]=qb.x; yb[4*f4+1]=qb.y; yb[4*f4+2]=qb.z; yb[4*f4+3]=qb.w;
        }
#pragma unroll
        for (int f = (DF / 4) * 4; f < DF; f++) { ya[f] = pa[f]; yb[f] = pb[f]; }
#pragma unroll
        for (int f = 0; f < DF; f++) yAB[f] = pack2(ya[f], yb[f]);
    }

    // ---- packed tmp[v=m][o] for the (A,B) pair ----
    u64 tAB[DOUT];
#pragma unroll
    for (int o = 0; o < DOUT; o++) tAB[o] = 0ull;

#pragma unroll
    for (int f = 0; f < DF; f++) {
#pragma unroll
        for (int o = 0; o < DOUT; o++) {
            float c0 = cg_c[CGOFF + (o * DI + 0) * DF + f];
            u64 g = fmul2(FAB[FB0], pack2(c0, c0));
#pragma unroll
            for (int i = 1; i < DI; i++) {
                float c = cg_c[CGOFF + (o * DI + i) * DF + f];
                g = ffma2(FAB[FB0 + i], pack2(c, c), g);
            }
            tAB[o] = ffma2(yAB[f], g, tAB[o]);
        }
    }

    // ---- publish tmp scalars to warp scratch ----
    __syncwarp();
#pragma unroll
    for (int o = 0; o < DOUT; o++) {
        float lo, hi; unpack2(tAB[o], lo, hi);
        tmp_w[ leA      * TMP_ESTR + o * 16 + m] = lo;
        tmp_w[(leA + 1) * TMP_ESTR + o * 16 + m] = hi;
    }
    __syncwarp();

    // ---- W: r-outer, radS loads hoisted across both v-quads ----
    const float* row = Rt + m * VSTRIDE + eh * 8;
    u64 wP[4][2][2];
#pragma unroll
    for (int j = 0; j < 4; j++)
#pragma unroll
        for (int g = 0; g < 2; g++) { wP[j][g][0] = 0ull; wP[j][g][1] = 0ull; }

#pragma unroll
    for (int r = 0; r < N_RBF; r++) {
        float4 rd0 = *(const float4*)(radS_w + r * 8);
        float4 rd1 = *(const float4*)(radS_w + r * 8 + 4);
        u64 d0 = pack2(rd0.x, rd0.y);
        u64 d1 = pack2(rd0.z, rd0.w);
        u64 d2 = pack2(rd1.x, rd1.y);
        u64 d3 = pack2(rd1.z, rd1.w);
        float4 q0 = *(const float4*)(row + r * RSLICE);
        float4 q1 = *(const float4*)(row + r * RSLICE + 4);
        u64 q00 = pack2(q0.x, q0.y), q01 = pack2(q0.z, q0.w);
        u64 q10 = pack2(q1.x, q1.y), q11 = pack2(q1.z, q1.w);
        wP[0][0][0] = ffma2(d0, q00, wP[0][0][0]);
        wP[0][0][1] = ffma2(d0, q01, wP[0][0][1]);
        wP[0][1][0] = ffma2(d0, q10, wP[0][1][0]);
        wP[0][1][1] = ffma2(d0, q11, wP[0][1][1]);
        wP[1][0][0] = ffma2(d1, q00, wP[1][0][0]);
        wP[1][0][1] = ffma2(d1, q01, wP[1][0][1]);
        wP[1][1][0] = ffma2(d1, q10, wP[1][1][0]);
        wP[1][1][1] = ffma2(d1, q11, wP[1][1][1]);
        wP[2][0][0] = ffma2(d2, q00, wP[2][0][0]);
        wP[2][0][1] = ffma2(d2, q01, wP[2][0][1]);
        wP[2][1][0] = ffma2(d2, q10, wP[2][1][0]);
        wP[2][1][1] = ffma2(d2, q11, wP[2][1][1]);
        wP[3][0][0] = ffma2(d3, q00, wP[3][0][0]);
        wP[3][0][1] = ffma2(d3, q01, wP[3][0][1]);
        wP[3][1][0] = ffma2(d3, q10, wP[3][1][0]);
        wP[3][1][1] = ffma2(d3, q11, wP[3][1][1]);
    }

    // ---- apply ----
#pragma unroll
    for (int g = 0; g < 2; g++) {
        const int v0 = eh * 8 + g * 4;
#pragma unroll
        for (int j = 0; j < 4; j++) {
#pragma unroll
            for (int o = 0; o < DOUT; o++) {
                float4 tf = *(const float4*)(tmp_w + j * TMP_ESTR + o * 16 + v0);
                u64 t01 = pack2(tf.x, tf.y), t23 = pack2(tf.z, tf.w);
                acc[j][o] = ffma2(wP[j][g][0], t01, acc[j][o]);
                acc[j][o] = ffma2(wP[j][g][1], t23, acc[j][o]);
            }
        }
    }
}

// ---------------------------------------------------------------------------
__global__ void __launch_bounds__(THREADS, 1)
conv_kernel(const float* __restrict__ features,
            const float* __restrict__ Ys,
            const float* __restrict__ radii,
            const float* __restrict__ n_norm,
            const int*   __restrict__ map_a,
            const int*   __restrict__ map_b,
            float* __restrict__ out)
{
    extern __shared__ __align__(16) float smem[];
    float* Rt    = smem + OFF_RT;      // [3][RBUF]
    float* tmp_s = smem + OFF_TMP;     // [NWARP][TMP_WARP]
    float* Ys_p  = smem + OFF_YS;      // [TILE_E][YS_STR]
    float* radS  = smem + OFF_RAD;     // [NWARP][RADS_WARP]

    const int tid  = threadIdx.x;
    const int warp = tid >> 5;
    const int lane = tid & 31;
    const int m    = lane & 15;
    const int eh   = lane >> 4;
    const int e0   = blockIdx.x * TILE_E;
    const int leA  = eh * 2;
    const int lA   = warp * 4 + leA;
    const int lB   = lA + 1;
    float* tmp_w   = tmp_s + warp * TMP_WARP;
    const float* radS_w = radS + warp * RADS_WARP;

    const uint32_t rt_sm = (uint32_t)__cvta_generic_to_shared(Rt);

#define ISSUE(P, BUF)                                                          \
    do {                                                                       \
        uint32_t base = rt_sm + (uint32_t)(BUF) * (RBUF * 4);                  \
        const float* src0 = R_pad + (size_t)(P) * RBUF;                        \
        _Pragma("unroll")                                                      \
        for (int c = tid; c < RBUF / 4; c += THREADS) {                        \
            asm volatile("cp.async.ca.shared.global [%0], [%1], 16;"           \
                         :: "r"(base + (uint32_t)(c * 16)), "l"(src0 + c * 4));\
        }                                                                      \
    } while (0)

#define COMMITG() asm volatile("cp.async.commit_group;" ::: "memory")

    ISSUE(0, 0); COMMITG();
    ISSUE(1, 1); COMMITG();

    // ---- stage padded Ys ----
    for (int idx = tid; idx < TILE_E * 25; idx += THREADS) {
        int le = idx / 25, f = idx - le * 25;
        int e  = e0 + le;
        int off = (f < 1) ? f : (f < 4) ? 3 + f : (f < 9) ? 8 + f
                : (f < 16) ? 11 + f : 12 + f;
        Ys_p[le * YS_STR + off] = (e < N_EDGES) ? Ys[(size_t)e * 25 + f] : 0.f;
    }

    // ---- per-warp duplicated radial table ----
    for (int idx = lane; idx < RADS_WARP; idx += 32) {
        int r = idx >> 3, j = (idx & 7) >> 1;
        int e = e0 + warp * 4 + j;
        bool v = (e < N_EDGES);
        radS[warp * RADS_WARP + idx] =
            v ? radii[(size_t)(v ? e : 0) * N_RBF + r] : 0.f;
    }

    // ---- per-lane bindings ----
    const int eA = e0 + lA, eB = e0 + lB;
    const bool vA = (eA < N_EDGES), vB = (eB < N_EDGES);
    const int eAc = vA ? eA : 0, eBc = vB ? eB : 0;

    u64 FAB[9];
    {
        const float* fA = features + (size_t)map_b[eAc] * FEAT;
        const float* fB = features + (size_t)map_b[eBc] * FEAT;
        FAB[0] = pack2(fA[m], fB[m]);
#pragma unroll
        for (int i = 0; i < 3; i++)
            FAB[1 + i] = pack2(fA[16 + m * 3 + i], fB[16 + m * 3 + i]);
#pragma unroll
        for (int i = 0; i < 5; i++)
            FAB[4 + i] = pack2(fA[64 + m * 5 + i], fB[64 + m * 5 + i]);
    }

    const int   aA  = map_a[eAc];
    const int   aB  = map_a[eBc];
    const float nnA = vA ? n_norm[aA] : 0.f;
    const float nnB = vB ? n_norm[aB] : 0.f;

    u64 acc[4][5];
#pragma unroll
    for (int j = 0; j < 4; j++)
#pragma unroll
        for (int o = 0; o < 5; o++) acc[j][o] = 0ull;

    __syncthreads();   // Ys_p, radS visible

#define STEP(P, IO, II, LF, CGOFF)                                             \
    do {                                                                       \
        if ((P) < 18)                                                          \
            asm volatile("cp.async.wait_group 1;" ::: "memory");               \
        else                                                                   \
            asm volatile("cp.async.wait_group 0;" ::: "memory");               \
        __syncthreads();                                                       \
        if ((P) < 17) { ISSUE((P) + 2, ((P) + 2) % 3); COMMITG(); }            \
        do_path<IO, II, LF, CGOFF>(FAB, Ys_p, Rt + ((P) % 3) * RBUF, tmp_w,    \
                                   radS_w, m, eh, lA, lB, leA, acc);           \
    } while (0)

#define EMIT(DOUT, EXPR_IDX)                                                   \
    do {                                                                       \
        float tot[4][DOUT];                                                    \
        _Pragma("unroll")                                                      \
        for (int j = 0; j < 4; j++)                                            \
            _Pragma("unroll")                                                  \
            for (int o = 0; o < (DOUT); o++) {                                 \
                u64 s = fadd2(acc[j][o],                                       \
                              __shfl_xor_sync(0xffffffffu, acc[j][o], 16));    \
                float lo, hi; unpack2(s, lo, hi);                              \
                tot[j][o] = lo + hi;                                           \
            }                                                                  \
        _Pragma("unroll")                                                      \
        for (int o = 0; o < (DOUT); o++) {                                     \
            if (vA) atomicAdd(&out[(size_t)aA * FEAT + (EXPR_IDX)],            \
                              nnA * tot[leA][o]);                              \
            if (vB) atomicAdd(&out[(size_t)aB * FEAT + (EXPR_IDX)],            \
                              nnB * tot[leA + 1][o]);                          \
        }                                                                      \
    } while (0)

#define CLEAR()                                                                \
    do {                                                                       \
        _Pragma("unroll")                                                      \
        for (int j = 0; j < 4; j++)                                            \
            _Pragma("unroll")                                                  \
            for (int o = 0; o < 5; o++) acc[j][o] = 0ull;                      \
    } while (0)

    // ---------------- io = 0 ------------------------------------------------
    STEP(0, 0, 0, 0, 0);
    STEP(1, 0, 1, 1, 1);
    STEP(2, 0, 2, 2, 10);
    EMIT(1, m);
    CLEAR();

    // ---------------- io = 1 ------------------------------------------------
    STEP(3, 1, 0, 1, 35);
    STEP(4, 1, 1, 0, 44);
    STEP(5, 1, 1, 1, 53);
    STEP(6, 1, 1, 2, 80);
    STEP(7, 1, 2, 1, 125);
    STEP(8, 1, 2, 2, 170);
    STEP(9, 1, 2, 3, 245);
    EMIT(3, 16 + m * 3 + o);
    CLEAR();

    // ---------------- io = 2 ------------------------------------------------
    STEP(10, 2, 0, 2, 350);
    STEP(11, 2, 1, 1, 375);
    STEP(12, 2, 1, 2, 420);
    STEP(13, 2, 1, 3, 495);
    STEP(14, 2, 2, 0, 600);
    STEP(15, 2, 2, 1, 625);
    STEP(16, 2, 2, 2, 700);
    STEP(17, 2, 2, 3, 825);
    STEP(18, 2, 2, 4, 1000);
    EMIT(5, 64 + m * 5 + o);

#undef STEP
#undef EMIT
#undef CLEAR
#undef ISSUE
#undef COMMITG
}

// ---------------------------------------------------------------------------
extern "C" void kernel_launch(void* const* d_in, const int* in_sizes, int n_in,
                              void* d_out, int out_size)
{
    const float* features = (const float*)d_in[0];
    const float* R        = (const float*)d_in[1];
    const float* Ys       = (const float*)d_in[2];
    const float* radii    = (const float*)d_in[3];
    const float* cg       = (const float*)d_in[4];
    const float* n_norm   = (const float*)d_in[5];
    const int*   map_a    = (const int*)d_in[6];
    const int*   map_b    = (const int*)d_in[7];
    float*       out      = (float*)d_out;

    static bool attr_done = false;
    if (!attr_done) {
        cudaFuncSetAttribute(conv_kernel,
                             cudaFuncAttributeMaxDynamicSharedMemorySize,
                             SMEM_BYTES);
        attr_done = true;
    }

    cudaMemcpyToSymbolAsync(cg_c, cg, 1225 * sizeof(float), 0,
                            cudaMemcpyDeviceToDevice, 0);
    cudaMemsetAsync(out, 0, (size_t)out_size * sizeof(float));

    prep_kernel<<<(NPATH * RBUF + 255) / 256, 256>>>(R);

    int grid = (N_EDGES + TILE_E - 1) / TILE_E;   // 3907
    conv_kernel<<<grid, THREADS, SMEM_BYTES>>>(features, Ys, radii, n_norm,
                                               map_a, map_b, out);
}